// round 15
// baseline (speedup 1.0000x reference)
#include <cuda_runtime.h>
#include <cuda_bf16.h>
#include <math_constants.h>
#include <cstdint>

// Problem constants
#define NN      20000
#define EE      320000
#define NODE_D  128
#define EDGE_D  16
#define HC      512       // HEADS*EMB
#define HEADS   4
#define EMB     128
#define HIDDEN  512
#define OUTD    64
#define NEG_SLOPE 0.2f

// ---------------- scratch (device globals; no allocation allowed) -------------
__device__ int   g_is64;
__device__ int   g_cnt[NN];
__device__ int   g_off[NN + 1];
__device__ int   g_cur[NN];
__device__ int   g_csr_src[EE];
__device__ int   g_csr_eid[EE];
__device__ float g_loop[NN * EDGE_D];
__device__ float g_Wp[HC * 1024];             // packed+rounded weights (max 512x1024)
__device__ float g_bp[1024];                  // packed bias
__device__ float g_xA[(size_t)NN * NODE_D];   // tf32-rounded copy of x
__device__ float g_xlr[(size_t)NN * 1024];    // [N][1024]: xl | xr (reused as decoder hidden)
__device__ float g_h[(size_t)NN * HC];        // layer outputs (tf32-rounded)

// ---------------- helpers -----------------------------------------------------
__device__ __forceinline__ int edge_val(const void* p, int is64, long long i) {
    return is64 ? (int)((const long long*)p)[i] : ((const int*)p)[i];
}

__device__ __forceinline__ float rna_tf32(float f) {
    unsigned u;
    asm("cvt.rna.tf32.f32 %0, %1;" : "=r"(u) : "f"(f));
    return __uint_as_float(u);
}

// zero counters + detect int64 vs int32 edge_index
__global__ void init_kernel(const void* eidx) {
    int i = blockIdx.x * blockDim.x + threadIdx.x;
    if (i < NN) { g_cnt[i] = 0; g_cur[i] = 0; }
    if (i == 0) {
        const unsigned* p = (const unsigned*)eidx;
        int is64 = 1;
        for (int k = 0; k < 16; k++)
            if (p[2 * k + 1] != 0u) is64 = 0;
        g_is64 = is64;
    }
}

__global__ void count_kernel(const void* eidx) {
    int e = blockIdx.x * blockDim.x + threadIdx.x;
    if (e >= EE) return;
    int is64 = g_is64;
    int dst = edge_val(eidx, is64, (long long)EE + e);
    atomicAdd(&g_cnt[dst], 1);
}

__global__ __launch_bounds__(1024) void scan_kernel() {
    __shared__ int s[1024];
    int tid = threadIdx.x;
    const int per = (NN + 1023) >> 10;
    int start = tid * per;
    int sum = 0;
    for (int i = 0; i < per; i++) {
        int idx = start + i;
        if (idx < NN) sum += g_cnt[idx];
    }
    s[tid] = sum;
    __syncthreads();
    for (int o = 1; o < 1024; o <<= 1) {
        int v = 0;
        if (tid >= o) v = s[tid - o];
        __syncthreads();
        if (tid >= o) s[tid] += v;
        __syncthreads();
    }
    int base = (tid > 0) ? s[tid - 1] : 0;
    for (int i = 0; i < per; i++) {
        int idx = start + i;
        if (idx < NN) { g_off[idx] = base; base += g_cnt[idx]; }
    }
    if (tid == 1023) g_off[NN] = s[1023];
}

__global__ void scatter_kernel(const void* eidx) {
    int e = blockIdx.x * blockDim.x + threadIdx.x;
    if (e >= EE) return;
    int is64 = g_is64;
    int src = edge_val(eidx, is64, e);
    int dst = edge_val(eidx, is64, (long long)EE + e);
    int pos = g_off[dst] + atomicAdd(&g_cur[dst], 1);
    g_csr_src[pos] = src;
    g_csr_eid[pos] = e;
}

// self-loop attr = mean of incoming edge_attr (CSR-based, no atomics)
__global__ __launch_bounds__(128) void loopattr_kernel(const float* __restrict__ ea) {
    int n = blockIdx.x * 4 + (threadIdx.x >> 5);
    if (n >= NN) return;
    int lane = threadIdx.x & 31;
    int beg = g_off[n], end = g_off[n + 1];
    float sum = 0.f;
    if (lane < EDGE_D) {
        for (int i = beg; i < end; i++) {
            int eid = g_csr_eid[i];
            sum += __ldg(&ea[(size_t)eid * EDGE_D + lane]);
        }
        float c = (float)(end - beg);
        g_loop[n * EDGE_D + lane] = sum / fmaxf(c, 1.f);
    }
}

// tf32-round x into g_xA
__global__ void round_x_kernel(const float* __restrict__ x) {
    int i = blockIdx.x * blockDim.x + threadIdx.x;
    if (i < NN * NODE_D) g_xA[i] = rna_tf32(x[i]);
}

// pack [W0|W1] (split at col S) into g_Wp with tf32 rounding; bias into g_bp
__global__ void pack_kernel(const float* __restrict__ W0, const float* __restrict__ W1,
                            const float* __restrict__ b0, const float* __restrict__ b1,
                            int S, int Nn, int K) {
    int i = blockIdx.x * blockDim.x + threadIdx.x;
    if (i < K * Nn) {
        int k = i / Nn, j = i - k * Nn;
        float v = (j < S) ? W0[k * S + j] : W1[k * (Nn - S) + (j - S)];
        g_Wp[i] = rna_tf32(v);
    }
    if (i < Nn) g_bp[i] = (i < S) ? b0[i] : b1[i - S];
}

// ---------------- tf32 tensor-core GEMM (3-stage cp.async pipeline) -----------
// Templated on BN (CTA N-tile), BK (k-tile), MINCTA (min blocks/SM).
// Operands must already be tf32-rounded in memory. 256 threads.
__device__ __forceinline__ void cp16(uint32_t dst, const float* src, int sz) {
    asm volatile("cp.async.cg.shared.global [%0], [%1], 16, %2;\n"
                 :: "r"(dst), "l"(src), "r"(sz));
}
__device__ __forceinline__ void cp_commit() {
    asm volatile("cp.async.commit_group;\n" ::: "memory");
}

template<int BN, int BK, int MINCTA>
__global__ __launch_bounds__(256, MINCTA) void gemm_tc_kernel(
    const float* __restrict__ A, const float* __restrict__ B,
    const float* __restrict__ bias, float* __restrict__ C,
    int M, int Nn, int K, int relu, int round_out)
{
    constexpr int AS_STR = BK + 4;
    constexpr int BS_STR = BN + 8;
    constexpr int A_SZ   = 128 * AS_STR;
    constexpr int STAGE  = A_SZ + BK * BS_STR;
    constexpr int KS     = BK / 8;
    constexpr int NT     = BN / 32;          // n-subtiles per warp (4 N-warps)
    constexpr int A_CHUNKS = BK / 8;         // 16B chunks per thread for A
    constexpr int TPR_B  = 256 / BK;         // threads per B row
    constexpr int B_CHUNKS = BN / TPR_B / 4; // 16B chunks per thread for B

    extern __shared__ float sm[];

    int tid  = threadIdx.x;
    int warp = tid >> 5;
    int lane = tid & 31;
    int gid  = lane >> 2;
    int tg   = lane & 3;

    int warpM = (warp & 1) * 64;             // 2 warps over M
    int warpN = (warp >> 1) * (BN / 4);      // 4 warps over N

    int rowBase = blockIdx.y * 128;
    int colBase = blockIdx.x * BN;

    float acc[4][NT][4];
#pragma unroll
    for (int i = 0; i < 4; i++)
#pragma unroll
        for (int j = 0; j < NT; j++)
#pragma unroll
            for (int r = 0; r < 4; r++) acc[i][j][r] = 0.f;

    // loader indices
    int arow = tid >> 1;                     // 0..127
    int acol = (tid & 1) * (BK / 2);
    int brow = tid / TPR_B;                  // 0..BK-1
    int bcol = (tid % TPR_B) * (BN / TPR_B);
    int agrow = rowBase + arow;
    const float* aptr = A + (size_t)agrow * K + acol;
    int a_sz = (agrow < M) ? 16 : 0;

    uint32_t smem_u = (uint32_t)__cvta_generic_to_shared(sm);
    uint32_t as_u = smem_u + (arow * AS_STR + acol) * 4;
    uint32_t bs_u = smem_u + (A_SZ + brow * BS_STR + bcol) * 4;

    auto load_tiles = [&](int kt, int buf) {
        uint32_t ad = as_u + buf * (STAGE * 4);
        const float* ap = aptr + kt;
#pragma unroll
        for (int i = 0; i < A_CHUNKS; i++) cp16(ad + i * 16, ap + i * 4, a_sz);
        uint32_t bd = bs_u + buf * (STAGE * 4);
        const float* bp = B + (size_t)(kt + brow) * Nn + colBase + bcol;
#pragma unroll
        for (int i = 0; i < B_CHUNKS; i++) {
            int gcol = colBase + bcol + i * 4;
            cp16(bd + i * 16, bp + i * 4, (gcol < Nn) ? 16 : 0);
        }
    };

    int nTiles = K / BK;
    load_tiles(0, 0);
    cp_commit();
    if (nTiles > 1) {
        load_tiles(BK, 1);
        cp_commit();
    }

    int buf = 0;
    for (int t = 0; t < nTiles; t++) {
        if (t + 1 < nTiles) {
            asm volatile("cp.async.wait_group 1;\n" ::: "memory");
        } else {
            asm volatile("cp.async.wait_group 0;\n" ::: "memory");
        }
        __syncthreads();

        if (t + 2 < nTiles) {
            int nbuf = buf + 2; if (nbuf >= 3) nbuf -= 3;
            load_tiles((t + 2) * BK, nbuf);
            cp_commit();
        }

        const float* Ab = sm + buf * STAGE;
        const float* Bb = Ab + A_SZ;
#pragma unroll
        for (int ks = 0; ks < KS; ks++) {
            int k0 = ks * 8;
            unsigned af[4][4], bf[NT][2];
#pragma unroll
            for (int mt = 0; mt < 4; mt++) {
                int r = warpM + mt * 16;
                af[mt][0] = __float_as_uint(Ab[(r + gid) * AS_STR + k0 + tg]);
                af[mt][1] = __float_as_uint(Ab[(r + gid + 8) * AS_STR + k0 + tg]);
                af[mt][2] = __float_as_uint(Ab[(r + gid) * AS_STR + k0 + tg + 4]);
                af[mt][3] = __float_as_uint(Ab[(r + gid + 8) * AS_STR + k0 + tg + 4]);
            }
#pragma unroll
            for (int nt = 0; nt < NT; nt++) {
                int c = warpN + nt * 8;
                bf[nt][0] = __float_as_uint(Bb[(k0 + tg) * BS_STR + c + gid]);
                bf[nt][1] = __float_as_uint(Bb[(k0 + tg + 4) * BS_STR + c + gid]);
            }
#pragma unroll
            for (int mt = 0; mt < 4; mt++)
#pragma unroll
                for (int nt = 0; nt < NT; nt++) {
                    asm volatile(
                        "mma.sync.aligned.m16n8k8.row.col.f32.tf32.tf32.f32 "
                        "{%0,%1,%2,%3}, {%4,%5,%6,%7}, {%8,%9}, {%0,%1,%2,%3};"
                        : "+f"(acc[mt][nt][0]), "+f"(acc[mt][nt][1]),
                          "+f"(acc[mt][nt][2]), "+f"(acc[mt][nt][3])
                        : "r"(af[mt][0]), "r"(af[mt][1]), "r"(af[mt][2]), "r"(af[mt][3]),
                          "r"(bf[nt][0]), "r"(bf[nt][1]));
                }
        }
        buf++; if (buf >= 3) buf -= 3;
    }

    // epilogue
#pragma unroll
    for (int mt = 0; mt < 4; mt++) {
#pragma unroll
        for (int nt = 0; nt < NT; nt++) {
            int r0 = rowBase + warpM + mt * 16 + gid;
            int c0 = colBase + warpN + nt * 8 + tg * 2;
#pragma unroll
            for (int half = 0; half < 2; half++) {
                int row = r0 + half * 8;
                if (row < M) {
#pragma unroll
                    for (int j = 0; j < 2; j++) {
                        int col = c0 + j;
                        if (col < Nn) {
                            float v = acc[mt][nt][half * 2 + j] + bias[col];
                            if (relu) v = fmaxf(v, 0.f);
                            if (round_out) v = rna_tf32(v);
                            C[(size_t)row * Nn + col] = v;
                        }
                    }
                }
            }
        }
    }
}

#define SMEM_OF(BN, BK) (3 * (128 * ((BK) + 4) + (BK) * ((BN) + 8)) * 4)

// ---------------- GATv2 aggregation: 2 nodes / block, 4 edges / iteration ----
__global__ __launch_bounds__(256) void gat_kernel(
    const float* __restrict__ xlr,        // [N][1024] xl|xr
    const float* __restrict__ edge_attr,  // [E][16]
    const float* __restrict__ We,         // [16][512]
    const float* __restrict__ att,        // [512]
    const float* __restrict__ bias,       // [512]
    float* __restrict__ out)              // [N][512] (tf32-rounded: feeds GEMMs only)
{
    __shared__ float We_sh[EDGE_D * HC];
    for (int i = threadIdx.x; i < EDGE_D * HC; i += 256) We_sh[i] = We[i];
    __syncthreads();

    int w = (threadIdx.x >> 5) & 3;           // head
    int lane = threadIdx.x & 31;
    int n = blockIdx.x * 2 + (threadIdx.x >> 7);   // node
    if (n >= NN) return;
    int cbase = w * EMB + lane;
    const float* Wp = We_sh + cbase;

    float att0 = __ldg(&att[cbase]);
    float att1 = __ldg(&att[cbase + 32]);
    float att2 = __ldg(&att[cbase + 64]);
    float att3 = __ldg(&att[cbase + 96]);

    const float* xrp = xlr + (size_t)n * 1024 + HC + cbase;
    float xr0 = xrp[0], xr1 = xrp[32], xr2 = xrp[64], xr3 = xrp[96];

    float m = -CUDART_INF_F, den = 0.f;
    float a0 = 0.f, a1 = 0.f, a2 = 0.f, a3 = 0.f;

    int beg = g_off[n], end = g_off[n + 1];

    for (int i = beg; i <= end; i += 4) {
        // load up to 4 edges (invalid slots -> zeros; masked out at softmax)
        float ce[4];
        float cx[4][4];
#pragma unroll
        for (int j = 0; j < 4; j++) {
            int idx = i + j;
            if (idx <= end) {
                int src;
                const float* ea;
                if (idx < end) {
                    src = __ldg(&g_csr_src[idx]);
                    ea  = edge_attr + (size_t)__ldg(&g_csr_eid[idx]) * EDGE_D;
                } else {
                    src = n;
                    ea  = g_loop + (size_t)n * EDGE_D;
                }
                ce[j] = (lane < EDGE_D) ? __ldg(&ea[lane]) : 0.f;
                const float* xp = xlr + (size_t)src * 1024 + cbase;
                cx[j][0] = __ldg(&xp[0]);  cx[j][1] = __ldg(&xp[32]);
                cx[j][2] = __ldg(&xp[64]); cx[j][3] = __ldg(&xp[96]);
            } else {
                ce[j] = 0.f;
                cx[j][0] = cx[j][1] = cx[j][2] = cx[j][3] = 0.f;
            }
        }

        // ef accumulators (init with xr)
        float e[4][4];
#pragma unroll
        for (int j = 0; j < 4; j++) {
            e[j][0] = xr0; e[j][1] = xr1; e[j][2] = xr2; e[j][3] = xr3;
        }
#pragma unroll
        for (int d = 0; d < EDGE_D; d++) {
            float w0 = Wp[d * HC];
            float w1 = Wp[d * HC + 32];
            float w2 = Wp[d * HC + 64];
            float w3 = Wp[d * HC + 96];
#pragma unroll
            for (int j = 0; j < 4; j++) {
                float av = __shfl_sync(0xffffffffu, ce[j], d);
                e[j][0] = fmaf(av, w0, e[j][0]);
                e[j][1] = fmaf(av, w1, e[j][1]);
                e[j][2] = fmaf(av, w2, e[j][2]);
                e[j][3] = fmaf(av, w3, e[j][3]);
            }
        }

        float p[4];
#pragma unroll
        for (int j = 0; j < 4; j++) {
            float s0 = cx[j][0] + e[j][0];
            float s1 = cx[j][1] + e[j][1];
            float s2 = cx[j][2] + e[j][2];
            float s3 = cx[j][3] + e[j][3];
            float l0 = fmaxf(s0, NEG_SLOPE * s0);
            float l1 = fmaxf(s1, NEG_SLOPE * s1);
            float l2 = fmaxf(s2, NEG_SLOPE * s2);
            float l3 = fmaxf(s3, NEG_SLOPE * s3);
            float pv = l0 * att0;
            pv = fmaf(l1, att1, pv);
            pv = fmaf(l2, att2, pv);
            pv = fmaf(l3, att3, pv);
            p[j] = pv;
        }
#pragma unroll
        for (int o = 16; o > 0; o >>= 1) {
#pragma unroll
            for (int j = 0; j < 4; j++)
                p[j] += __shfl_xor_sync(0xffffffffu, p[j], o);
        }
#pragma unroll
        for (int j = 0; j < 4; j++)
            if (i + j > end) p[j] = -CUDART_INF_F;

        float nm = fmaxf(fmaxf(m, fmaxf(p[0], p[1])), fmaxf(p[2], p[3]));
        float corr = __expf(m - nm);
        float pe0 = __expf(p[0] - nm);
        float pe1 = __expf(p[1] - nm);
        float pe2 = __expf(p[2] - nm);
        float pe3 = __expf(p[3] - nm);
        den = den * corr + pe0 + pe1 + pe2 + pe3;
        a0 = a0 * corr + pe0 * cx[0][0] + pe1 * cx[1][0] + pe2 * cx[2][0] + pe3 * cx[3][0];
        a1 = a1 * corr + pe0 * cx[0][1] + pe1 * cx[1][1] + pe2 * cx[2][1] + pe3 * cx[3][1];
        a2 = a2 * corr + pe0 * cx[0][2] + pe1 * cx[1][2] + pe2 * cx[2][2] + pe3 * cx[3][2];
        a3 = a3 * corr + pe0 * cx[0][3] + pe1 * cx[1][3] + pe2 * cx[2][3] + pe3 * cx[3][3];
        m = nm;
    }
    float inv = 1.f / (den + 1e-16f);
    float* op = out + (size_t)n * HC + cbase;
    op[0]  = rna_tf32(fmaf(a0, inv, __ldg(&bias[cbase])));
    op[32] = rna_tf32(fmaf(a1, inv, __ldg(&bias[cbase + 32])));
    op[64] = rna_tf32(fmaf(a2, inv, __ldg(&bias[cbase + 64])));
    op[96] = rna_tf32(fmaf(a3, inv, __ldg(&bias[cbase + 96])));
}

// ---------------- launch ------------------------------------------------------
extern "C" void kernel_launch(void* const* d_in, const int* in_sizes, int n_in,
                              void* d_out, int out_size) {
    const float* x     = (const float*)d_in[0];
    const void*  eidx  = d_in[1];
    const float* eattr = (const float*)d_in[2];
    const float* Wl1   = (const float*)d_in[3];
    const float* bl1   = (const float*)d_in[4];
    const float* Wr1   = (const float*)d_in[5];
    const float* br1   = (const float*)d_in[6];
    const float* We1   = (const float*)d_in[7];
    const float* att1  = (const float*)d_in[8];
    const float* bias1 = (const float*)d_in[9];
    const float* Wl2   = (const float*)d_in[10];
    const float* bl2   = (const float*)d_in[11];
    const float* Wr2   = (const float*)d_in[12];
    const float* br2   = (const float*)d_in[13];
    const float* We2   = (const float*)d_in[14];
    const float* att2  = (const float*)d_in[15];
    const float* bias2 = (const float*)d_in[16];
    const float* Wd1   = (const float*)d_in[17];
    const float* bd1   = (const float*)d_in[18];
    const float* Wd2   = (const float*)d_in[19];
    const float* bd2   = (const float*)d_in[20];
    float* out = (float*)d_out;

    float* xlr; cudaGetSymbolAddress((void**)&xlr, g_xlr);
    float* h;   cudaGetSymbolAddress((void**)&h, g_h);
    float* xA;  cudaGetSymbolAddress((void**)&xA, g_xA);
    float* Wp;  cudaGetSymbolAddress((void**)&Wp, g_Wp);
    float* bp;  cudaGetSymbolAddress((void**)&bp, g_bp);

    cudaFuncSetAttribute((const void*)gemm_tc_kernel<128, 32, 2>,
                         cudaFuncAttributeMaxDynamicSharedMemorySize, SMEM_OF(128, 32));
    cudaFuncSetAttribute((const void*)gemm_tc_kernel<128, 16, 3>,
                         cudaFuncAttributeMaxDynamicSharedMemorySize, SMEM_OF(128, 16));
    cudaFuncSetAttribute((const void*)gemm_tc_kernel<64, 32, 2>,
                         cudaFuncAttributeMaxDynamicSharedMemorySize, SMEM_OF(64, 32));

    dim3 blk(256);
    dim3 grid_lr(1024 / 128, (NN + 127) / 128);
    dim3 grid_d1(HIDDEN / 128, (NN + 127) / 128);
    dim3 grid_d2(1, (NN + 127) / 128);   // OUTD=64 = BN

    // ---- layer-1 GEMM first (ncu capture lands here; BK=16/occ3 experiment) ----
    init_kernel<<<(NN + 255) / 256, 256>>>(eidx);
    round_x_kernel<<<(NN * NODE_D + 255) / 256, 256>>>(x);
    pack_kernel<<<(NODE_D * 1024 + 255) / 256, 256>>>(Wl1, Wr1, bl1, br1, HC, 1024, NODE_D);
    gemm_tc_kernel<128, 16, 3><<<grid_lr, blk, SMEM_OF(128, 16)>>>(xA, Wp, bp, xlr, NN, 1024, NODE_D, 0, 0);

    // ---- CSR preprocessing ----
    count_kernel<<<(EE + 255) / 256, 256>>>(eidx);
    scan_kernel<<<1, 1024>>>();
    scatter_kernel<<<(EE + 255) / 256, 256>>>(eidx);
    loopattr_kernel<<<(NN + 3) / 4, 128>>>(eattr);

    // ---- layer 1 aggregation ----
    gat_kernel<<<NN / 2, 256>>>(xlr, eattr, We1, att1, bias1, h);

    // ---- layer 2 ----
    pack_kernel<<<(HC * 1024 + 255) / 256, 256>>>(Wl2, Wr2, bl2, br2, HC, 1024, HC);
    gemm_tc_kernel<128, 32, 2><<<grid_lr, blk, SMEM_OF(128, 32)>>>(h, Wp, bp, xlr, NN, 1024, HC, 0, 0);
    gat_kernel<<<NN / 2, 256>>>(xlr, eattr, We2, att2, bias2, h);

    // ---- decoder ----
    float* hid = xlr;  // reuse scratch
    pack_kernel<<<(HC * HIDDEN + 255) / 256, 256>>>(Wd1, Wd1, bd1, bd1, HIDDEN, HIDDEN, HC);
    gemm_tc_kernel<128, 32, 2><<<grid_d1, blk, SMEM_OF(128, 32)>>>(h, Wp, bp, hid, NN, HIDDEN, HC, 1, 1);
    pack_kernel<<<(HIDDEN * OUTD + 255) / 256, 256>>>(Wd2, Wd2, bd2, bd2, OUTD, OUTD, HIDDEN);
    gemm_tc_kernel<64, 32, 2><<<grid_d2, blk, SMEM_OF(64, 32)>>>(hid, Wp, bp, out, NN, OUTD, HIDDEN, 0, 0);
}

// round 16
// speedup vs baseline: 1.0174x; 1.0174x over previous
#include <cuda_runtime.h>
#include <cuda_bf16.h>
#include <math_constants.h>
#include <cstdint>

// Problem constants
#define NN      20000
#define EE      320000
#define NODE_D  128
#define EDGE_D  16
#define HC      512       // HEADS*EMB
#define HEADS   4
#define EMB     128
#define HIDDEN  512
#define OUTD    64
#define NEG_SLOPE 0.2f

// ---------------- scratch (device globals; no allocation allowed) -------------
__device__ int   g_is64;
__device__ int   g_cnt[NN];
__device__ int   g_off[NN + 1];
__device__ int   g_cur[NN];
__device__ int   g_csr_src[EE];
__device__ int   g_csr_eid[EE];
__device__ float g_loop[NN * EDGE_D];
__device__ float g_Wp[HC * 1024];             // packed+rounded weights (max 512x1024)
__device__ float g_bp[1024];                  // packed bias
__device__ float g_xA[(size_t)NN * NODE_D];   // tf32-rounded copy of x
__device__ float g_xlr[(size_t)NN * 1024];    // [N][1024]: xl | xr (reused as decoder hidden)
__device__ float g_h[(size_t)NN * HC];        // layer outputs (tf32-rounded)

// ---------------- helpers -----------------------------------------------------
__device__ __forceinline__ int edge_val(const void* p, int is64, long long i) {
    return is64 ? (int)((const long long*)p)[i] : ((const int*)p)[i];
}

__device__ __forceinline__ float rna_tf32(float f) {
    unsigned u;
    asm("cvt.rna.tf32.f32 %0, %1;" : "=r"(u) : "f"(f));
    return __uint_as_float(u);
}

// zero counters + detect int64 vs int32 edge_index
__global__ void init_kernel(const void* eidx) {
    int i = blockIdx.x * blockDim.x + threadIdx.x;
    if (i < NN) { g_cnt[i] = 0; g_cur[i] = 0; }
    if (i == 0) {
        const unsigned* p = (const unsigned*)eidx;
        int is64 = 1;
        for (int k = 0; k < 16; k++)
            if (p[2 * k + 1] != 0u) is64 = 0;
        g_is64 = is64;
    }
}

__global__ void count_kernel(const void* eidx) {
    int e = blockIdx.x * blockDim.x + threadIdx.x;
    if (e >= EE) return;
    int is64 = g_is64;
    int dst = edge_val(eidx, is64, (long long)EE + e);
    atomicAdd(&g_cnt[dst], 1);
}

__global__ __launch_bounds__(1024) void scan_kernel() {
    __shared__ int s[1024];
    int tid = threadIdx.x;
    const int per = (NN + 1023) >> 10;
    int start = tid * per;
    int sum = 0;
    for (int i = 0; i < per; i++) {
        int idx = start + i;
        if (idx < NN) sum += g_cnt[idx];
    }
    s[tid] = sum;
    __syncthreads();
    for (int o = 1; o < 1024; o <<= 1) {
        int v = 0;
        if (tid >= o) v = s[tid - o];
        __syncthreads();
        if (tid >= o) s[tid] += v;
        __syncthreads();
    }
    int base = (tid > 0) ? s[tid - 1] : 0;
    for (int i = 0; i < per; i++) {
        int idx = start + i;
        if (idx < NN) { g_off[idx] = base; base += g_cnt[idx]; }
    }
    if (tid == 1023) g_off[NN] = s[1023];
}

__global__ void scatter_kernel(const void* eidx) {
    int e = blockIdx.x * blockDim.x + threadIdx.x;
    if (e >= EE) return;
    int is64 = g_is64;
    int src = edge_val(eidx, is64, e);
    int dst = edge_val(eidx, is64, (long long)EE + e);
    int pos = g_off[dst] + atomicAdd(&g_cur[dst], 1);
    g_csr_src[pos] = src;
    g_csr_eid[pos] = e;
}

// self-loop attr = mean of incoming edge_attr (CSR-based, no atomics)
__global__ __launch_bounds__(128) void loopattr_kernel(const float* __restrict__ ea) {
    int n = blockIdx.x * 4 + (threadIdx.x >> 5);
    if (n >= NN) return;
    int lane = threadIdx.x & 31;
    int beg = g_off[n], end = g_off[n + 1];
    float sum = 0.f;
    if (lane < EDGE_D) {
        for (int i = beg; i < end; i++) {
            int eid = g_csr_eid[i];
            sum += __ldg(&ea[(size_t)eid * EDGE_D + lane]);
        }
        float c = (float)(end - beg);
        g_loop[n * EDGE_D + lane] = sum / fmaxf(c, 1.f);
    }
}

// tf32-round x into g_xA
__global__ void round_x_kernel(const float* __restrict__ x) {
    int i = blockIdx.x * blockDim.x + threadIdx.x;
    if (i < NN * NODE_D) g_xA[i] = rna_tf32(x[i]);
}

// pack [W0|W1] (split at col S) into g_Wp with tf32 rounding; bias into g_bp
__global__ void pack_kernel(const float* __restrict__ W0, const float* __restrict__ W1,
                            const float* __restrict__ b0, const float* __restrict__ b1,
                            int S, int Nn, int K) {
    int i = blockIdx.x * blockDim.x + threadIdx.x;
    if (i < K * Nn) {
        int k = i / Nn, j = i - k * Nn;
        float v = (j < S) ? W0[k * S + j] : W1[k * (Nn - S) + (j - S)];
        g_Wp[i] = rna_tf32(v);
    }
    if (i < Nn) g_bp[i] = (i < S) ? b0[i] : b1[i - S];
}

// ---------------- tf32 tensor-core GEMM (3-stage cp.async pipeline) -----------
// Templated on BN (CTA N-tile), BK (k-tile), MINCTA (min blocks/SM).
// Operands must already be tf32-rounded in memory. 256 threads.
__device__ __forceinline__ void cp16(uint32_t dst, const float* src, int sz) {
    asm volatile("cp.async.cg.shared.global [%0], [%1], 16, %2;\n"
                 :: "r"(dst), "l"(src), "r"(sz));
}
__device__ __forceinline__ void cp_commit() {
    asm volatile("cp.async.commit_group;\n" ::: "memory");
}

template<int BN, int BK, int MINCTA>
__global__ __launch_bounds__(256, MINCTA) void gemm_tc_kernel(
    const float* __restrict__ A, const float* __restrict__ B,
    const float* __restrict__ bias, float* __restrict__ C,
    int M, int Nn, int K, int relu, int round_out)
{
    constexpr int AS_STR = BK + 4;
    constexpr int BS_STR = BN + 8;
    constexpr int A_SZ   = 128 * AS_STR;
    constexpr int STAGE  = A_SZ + BK * BS_STR;
    constexpr int KS     = BK / 8;
    constexpr int NT     = BN / 32;          // n-subtiles per warp (4 N-warps)
    constexpr int A_CHUNKS = BK / 8;         // 16B chunks per thread for A
    constexpr int TPR_B  = 256 / BK;         // threads per B row
    constexpr int B_CHUNKS = BN / TPR_B / 4; // 16B chunks per thread for B

    extern __shared__ float sm[];

    int tid  = threadIdx.x;
    int warp = tid >> 5;
    int lane = tid & 31;
    int gid  = lane >> 2;
    int tg   = lane & 3;

    int warpM = (warp & 1) * 64;             // 2 warps over M
    int warpN = (warp >> 1) * (BN / 4);      // 4 warps over N

    int rowBase = blockIdx.y * 128;
    int colBase = blockIdx.x * BN;

    float acc[4][NT][4];
#pragma unroll
    for (int i = 0; i < 4; i++)
#pragma unroll
        for (int j = 0; j < NT; j++)
#pragma unroll
            for (int r = 0; r < 4; r++) acc[i][j][r] = 0.f;

    // loader indices
    int arow = tid >> 1;                     // 0..127
    int acol = (tid & 1) * (BK / 2);
    int brow = tid / TPR_B;                  // 0..BK-1
    int bcol = (tid % TPR_B) * (BN / TPR_B);
    int agrow = rowBase + arow;
    const float* aptr = A + (size_t)agrow * K + acol;
    int a_sz = (agrow < M) ? 16 : 0;

    uint32_t smem_u = (uint32_t)__cvta_generic_to_shared(sm);
    uint32_t as_u = smem_u + (arow * AS_STR + acol) * 4;
    uint32_t bs_u = smem_u + (A_SZ + brow * BS_STR + bcol) * 4;

    auto load_tiles = [&](int kt, int buf) {
        uint32_t ad = as_u + buf * (STAGE * 4);
        const float* ap = aptr + kt;
#pragma unroll
        for (int i = 0; i < A_CHUNKS; i++) cp16(ad + i * 16, ap + i * 4, a_sz);
        uint32_t bd = bs_u + buf * (STAGE * 4);
        const float* bp = B + (size_t)(kt + brow) * Nn + colBase + bcol;
#pragma unroll
        for (int i = 0; i < B_CHUNKS; i++) {
            int gcol = colBase + bcol + i * 4;
            cp16(bd + i * 16, bp + i * 4, (gcol < Nn) ? 16 : 0);
        }
    };

    int nTiles = K / BK;
    load_tiles(0, 0);
    cp_commit();
    if (nTiles > 1) {
        load_tiles(BK, 1);
        cp_commit();
    }

    int buf = 0;
    for (int t = 0; t < nTiles; t++) {
        if (t + 1 < nTiles) {
            asm volatile("cp.async.wait_group 1;\n" ::: "memory");
        } else {
            asm volatile("cp.async.wait_group 0;\n" ::: "memory");
        }
        __syncthreads();

        if (t + 2 < nTiles) {
            int nbuf = buf + 2; if (nbuf >= 3) nbuf -= 3;
            load_tiles((t + 2) * BK, nbuf);
            cp_commit();
        }

        const float* Ab = sm + buf * STAGE;
        const float* Bb = Ab + A_SZ;
#pragma unroll
        for (int ks = 0; ks < KS; ks++) {
            int k0 = ks * 8;
            unsigned af[4][4], bf[NT][2];
#pragma unroll
            for (int mt = 0; mt < 4; mt++) {
                int r = warpM + mt * 16;
                af[mt][0] = __float_as_uint(Ab[(r + gid) * AS_STR + k0 + tg]);
                af[mt][1] = __float_as_uint(Ab[(r + gid + 8) * AS_STR + k0 + tg]);
                af[mt][2] = __float_as_uint(Ab[(r + gid) * AS_STR + k0 + tg + 4]);
                af[mt][3] = __float_as_uint(Ab[(r + gid + 8) * AS_STR + k0 + tg + 4]);
            }
#pragma unroll
            for (int nt = 0; nt < NT; nt++) {
                int c = warpN + nt * 8;
                bf[nt][0] = __float_as_uint(Bb[(k0 + tg) * BS_STR + c + gid]);
                bf[nt][1] = __float_as_uint(Bb[(k0 + tg + 4) * BS_STR + c + gid]);
            }
#pragma unroll
            for (int mt = 0; mt < 4; mt++)
#pragma unroll
                for (int nt = 0; nt < NT; nt++) {
                    asm volatile(
                        "mma.sync.aligned.m16n8k8.row.col.f32.tf32.tf32.f32 "
                        "{%0,%1,%2,%3}, {%4,%5,%6,%7}, {%8,%9}, {%0,%1,%2,%3};"
                        : "+f"(acc[mt][nt][0]), "+f"(acc[mt][nt][1]),
                          "+f"(acc[mt][nt][2]), "+f"(acc[mt][nt][3])
                        : "r"(af[mt][0]), "r"(af[mt][1]), "r"(af[mt][2]), "r"(af[mt][3]),
                          "r"(bf[nt][0]), "r"(bf[nt][1]));
                }
        }
        buf++; if (buf >= 3) buf -= 3;
    }

    // epilogue
#pragma unroll
    for (int mt = 0; mt < 4; mt++) {
#pragma unroll
        for (int nt = 0; nt < NT; nt++) {
            int r0 = rowBase + warpM + mt * 16 + gid;
            int c0 = colBase + warpN + nt * 8 + tg * 2;
#pragma unroll
            for (int half = 0; half < 2; half++) {
                int row = r0 + half * 8;
                if (row < M) {
#pragma unroll
                    for (int j = 0; j < 2; j++) {
                        int col = c0 + j;
                        if (col < Nn) {
                            float v = acc[mt][nt][half * 2 + j] + bias[col];
                            if (relu) v = fmaxf(v, 0.f);
                            if (round_out) v = rna_tf32(v);
                            C[(size_t)row * Nn + col] = v;
                        }
                    }
                }
            }
        }
    }
}

#define SMEM_OF(BN, BK) (3 * (128 * ((BK) + 4) + (BK) * ((BN) + 8)) * 4)

// ---------------- GATv2 aggregation: 2 nodes / block, 4 edges / iteration ----
__global__ __launch_bounds__(256) void gat_kernel(
    const float* __restrict__ xlr,        // [N][1024] xl|xr
    const float* __restrict__ edge_attr,  // [E][16]
    const float* __restrict__ We,         // [16][512]
    const float* __restrict__ att,        // [512]
    const float* __restrict__ bias,       // [512]
    float* __restrict__ out)              // [N][512] (tf32-rounded: feeds GEMMs only)
{
    __shared__ float We_sh[EDGE_D * HC];
    for (int i = threadIdx.x; i < EDGE_D * HC; i += 256) We_sh[i] = We[i];
    __syncthreads();

    int w = (threadIdx.x >> 5) & 3;           // head
    int lane = threadIdx.x & 31;
    int n = blockIdx.x * 2 + (threadIdx.x >> 7);   // node
    if (n >= NN) return;
    int cbase = w * EMB + lane;
    const float* Wp = We_sh + cbase;

    float att0 = __ldg(&att[cbase]);
    float att1 = __ldg(&att[cbase + 32]);
    float att2 = __ldg(&att[cbase + 64]);
    float att3 = __ldg(&att[cbase + 96]);

    const float* xrp = xlr + (size_t)n * 1024 + HC + cbase;
    float xr0 = xrp[0], xr1 = xrp[32], xr2 = xrp[64], xr3 = xrp[96];

    float m = -CUDART_INF_F, den = 0.f;
    float a0 = 0.f, a1 = 0.f, a2 = 0.f, a3 = 0.f;

    int beg = g_off[n], end = g_off[n + 1];

    for (int i = beg; i <= end; i += 4) {
        // load up to 4 edges (invalid slots -> zeros; masked out at softmax)
        float ce[4];
        float cx[4][4];
#pragma unroll
        for (int j = 0; j < 4; j++) {
            int idx = i + j;
            if (idx <= end) {
                int src;
                const float* ea;
                if (idx < end) {
                    src = __ldg(&g_csr_src[idx]);
                    ea  = edge_attr + (size_t)__ldg(&g_csr_eid[idx]) * EDGE_D;
                } else {
                    src = n;
                    ea  = g_loop + (size_t)n * EDGE_D;
                }
                ce[j] = (lane < EDGE_D) ? __ldg(&ea[lane]) : 0.f;
                const float* xp = xlr + (size_t)src * 1024 + cbase;
                cx[j][0] = __ldg(&xp[0]);  cx[j][1] = __ldg(&xp[32]);
                cx[j][2] = __ldg(&xp[64]); cx[j][3] = __ldg(&xp[96]);
            } else {
                ce[j] = 0.f;
                cx[j][0] = cx[j][1] = cx[j][2] = cx[j][3] = 0.f;
            }
        }

        // ef accumulators (init with xr)
        float e[4][4];
#pragma unroll
        for (int j = 0; j < 4; j++) {
            e[j][0] = xr0; e[j][1] = xr1; e[j][2] = xr2; e[j][3] = xr3;
        }
#pragma unroll
        for (int d = 0; d < EDGE_D; d++) {
            float w0 = Wp[d * HC];
            float w1 = Wp[d * HC + 32];
            float w2 = Wp[d * HC + 64];
            float w3 = Wp[d * HC + 96];
#pragma unroll
            for (int j = 0; j < 4; j++) {
                float av = __shfl_sync(0xffffffffu, ce[j], d);
                e[j][0] = fmaf(av, w0, e[j][0]);
                e[j][1] = fmaf(av, w1, e[j][1]);
                e[j][2] = fmaf(av, w2, e[j][2]);
                e[j][3] = fmaf(av, w3, e[j][3]);
            }
        }

        float p[4];
#pragma unroll
        for (int j = 0; j < 4; j++) {
            float s0 = cx[j][0] + e[j][0];
            float s1 = cx[j][1] + e[j][1];
            float s2 = cx[j][2] + e[j][2];
            float s3 = cx[j][3] + e[j][3];
            float l0 = fmaxf(s0, NEG_SLOPE * s0);
            float l1 = fmaxf(s1, NEG_SLOPE * s1);
            float l2 = fmaxf(s2, NEG_SLOPE * s2);
            float l3 = fmaxf(s3, NEG_SLOPE * s3);
            float pv = l0 * att0;
            pv = fmaf(l1, att1, pv);
            pv = fmaf(l2, att2, pv);
            pv = fmaf(l3, att3, pv);
            p[j] = pv;
        }
#pragma unroll
        for (int o = 16; o > 0; o >>= 1) {
#pragma unroll
            for (int j = 0; j < 4; j++)
                p[j] += __shfl_xor_sync(0xffffffffu, p[j], o);
        }
#pragma unroll
        for (int j = 0; j < 4; j++)
            if (i + j > end) p[j] = -CUDART_INF_F;

        float nm = fmaxf(fmaxf(m, fmaxf(p[0], p[1])), fmaxf(p[2], p[3]));
        float corr = __expf(m - nm);
        float pe0 = __expf(p[0] - nm);
        float pe1 = __expf(p[1] - nm);
        float pe2 = __expf(p[2] - nm);
        float pe3 = __expf(p[3] - nm);
        den = den * corr + pe0 + pe1 + pe2 + pe3;
        a0 = a0 * corr + pe0 * cx[0][0] + pe1 * cx[1][0] + pe2 * cx[2][0] + pe3 * cx[3][0];
        a1 = a1 * corr + pe0 * cx[0][1] + pe1 * cx[1][1] + pe2 * cx[2][1] + pe3 * cx[3][1];
        a2 = a2 * corr + pe0 * cx[0][2] + pe1 * cx[1][2] + pe2 * cx[2][2] + pe3 * cx[3][2];
        a3 = a3 * corr + pe0 * cx[0][3] + pe1 * cx[1][3] + pe2 * cx[2][3] + pe3 * cx[3][3];
        m = nm;
    }
    float inv = 1.f / (den + 1e-16f);
    float* op = out + (size_t)n * HC + cbase;
    op[0]  = rna_tf32(fmaf(a0, inv, __ldg(&bias[cbase])));
    op[32] = rna_tf32(fmaf(a1, inv, __ldg(&bias[cbase + 32])));
    op[64] = rna_tf32(fmaf(a2, inv, __ldg(&bias[cbase + 64])));
    op[96] = rna_tf32(fmaf(a3, inv, __ldg(&bias[cbase + 96])));
}

// ---------------- launch ------------------------------------------------------
extern "C" void kernel_launch(void* const* d_in, const int* in_sizes, int n_in,
                              void* d_out, int out_size) {
    const float* x     = (const float*)d_in[0];
    const void*  eidx  = d_in[1];
    const float* eattr = (const float*)d_in[2];
    const float* Wl1   = (const float*)d_in[3];
    const float* bl1   = (const float*)d_in[4];
    const float* Wr1   = (const float*)d_in[5];
    const float* br1   = (const float*)d_in[6];
    const float* We1   = (const float*)d_in[7];
    const float* att1  = (const float*)d_in[8];
    const float* bias1 = (const float*)d_in[9];
    const float* Wl2   = (const float*)d_in[10];
    const float* bl2   = (const float*)d_in[11];
    const float* Wr2   = (const float*)d_in[12];
    const float* br2   = (const float*)d_in[13];
    const float* We2   = (const float*)d_in[14];
    const float* att2  = (const float*)d_in[15];
    const float* bias2 = (const float*)d_in[16];
    const float* Wd1   = (const float*)d_in[17];
    const float* bd1   = (const float*)d_in[18];
    const float* Wd2   = (const float*)d_in[19];
    const float* bd2   = (const float*)d_in[20];
    float* out = (float*)d_out;

    float* xlr; cudaGetSymbolAddress((void**)&xlr, g_xlr);
    float* h;   cudaGetSymbolAddress((void**)&h, g_h);
    float* xA;  cudaGetSymbolAddress((void**)&xA, g_xA);
    float* Wp;  cudaGetSymbolAddress((void**)&Wp, g_Wp);
    float* bp;  cudaGetSymbolAddress((void**)&bp, g_bp);

    cudaFuncSetAttribute((const void*)gemm_tc_kernel<128, 32, 2>,
                         cudaFuncAttributeMaxDynamicSharedMemorySize, SMEM_OF(128, 32));
    cudaFuncSetAttribute((const void*)gemm_tc_kernel<64, 32, 2>,
                         cudaFuncAttributeMaxDynamicSharedMemorySize, SMEM_OF(64, 32));

    dim3 blk(256);
    dim3 grid_lr(1024 / 128, (NN + 127) / 128);
    dim3 grid_d1(HIDDEN / 128, (NN + 127) / 128);
    dim3 grid_d2(1, (NN + 127) / 128);   // OUTD=64 = BN

    // ---- layer-1 GEMM first (ncu capture lands here) ----
    init_kernel<<<(NN + 255) / 256, 256>>>(eidx);
    round_x_kernel<<<(NN * NODE_D + 255) / 256, 256>>>(x);
    pack_kernel<<<(NODE_D * 1024 + 255) / 256, 256>>>(Wl1, Wr1, bl1, br1, HC, 1024, NODE_D);
    gemm_tc_kernel<128, 32, 2><<<grid_lr, blk, SMEM_OF(128, 32)>>>(xA, Wp, bp, xlr, NN, 1024, NODE_D, 0, 0);

    // ---- CSR preprocessing ----
    count_kernel<<<(EE + 255) / 256, 256>>>(eidx);
    scan_kernel<<<1, 1024>>>();
    scatter_kernel<<<(EE + 255) / 256, 256>>>(eidx);
    loopattr_kernel<<<(NN + 3) / 4, 128>>>(eattr);

    // ---- layer 1 aggregation ----
    gat_kernel<<<NN / 2, 256>>>(xlr, eattr, We1, att1, bias1, h);

    // ---- layer 2 ----
    pack_kernel<<<(HC * 1024 + 255) / 256, 256>>>(Wl2, Wr2, bl2, br2, HC, 1024, HC);
    gemm_tc_kernel<128, 32, 2><<<grid_lr, blk, SMEM_OF(128, 32)>>>(h, Wp, bp, xlr, NN, 1024, HC, 0, 0);
    gat_kernel<<<NN / 2, 256>>>(xlr, eattr, We2, att2, bias2, h);

    // ---- decoder ----
    float* hid = xlr;  // reuse scratch
    pack_kernel<<<(HC * HIDDEN + 255) / 256, 256>>>(Wd1, Wd1, bd1, bd1, HIDDEN, HIDDEN, HC);
    gemm_tc_kernel<128, 32, 2><<<grid_d1, blk, SMEM_OF(128, 32)>>>(h, Wp, bp, hid, NN, HIDDEN, HC, 1, 1);
    pack_kernel<<<(HIDDEN * OUTD + 255) / 256, 256>>>(Wd2, Wd2, bd2, bd2, OUTD, OUTD, HIDDEN);
    gemm_tc_kernel<64, 32, 2><<<grid_d2, blk, SMEM_OF(64, 32)>>>(hid, Wp, bp, out, NN, OUTD, HIDDEN, 0, 0);
}

// round 17
// speedup vs baseline: 1.0342x; 1.0165x over previous
#include <cuda_runtime.h>
#include <cuda_bf16.h>
#include <math_constants.h>
#include <cstdint>

// Problem constants
#define NN      20000
#define EE      320000
#define NODE_D  128
#define EDGE_D  16
#define HC      512       // HEADS*EMB
#define HEADS   4
#define EMB     128
#define HIDDEN  512
#define OUTD    64
#define NEG_SLOPE 0.2f

// ---------------- scratch (device globals; no allocation allowed) -------------
__device__ int   g_is64;
__device__ int   g_cnt[NN];
__device__ int   g_off[NN + 1];
__device__ int   g_cur[NN];
__device__ int   g_csr_src[EE];
__device__ int   g_csr_eid[EE];
__device__ float g_loop[NN * EDGE_D];
__device__ float g_Wp[HC * 1024];             // packed+rounded weights (max 512x1024)
__device__ float g_bp[1024];                  // packed bias
__device__ float g_Wpd2[HIDDEN * OUTD];       // decoder-2 packed weights
__device__ float g_bpd2[OUTD];
__device__ float g_xA[(size_t)NN * NODE_D];   // tf32-rounded copy of x
__device__ float g_xlr[(size_t)NN * 1024];    // [N][1024]: xl | xr (reused as decoder hidden)
__device__ float g_h[(size_t)NN * HC];        // layer outputs (tf32-rounded)

// ---------------- helpers -----------------------------------------------------
__device__ __forceinline__ int edge_val(const void* p, int is64, long long i) {
    return is64 ? (int)((const long long*)p)[i] : ((const int*)p)[i];
}

__device__ __forceinline__ float rna_tf32(float f) {
    unsigned u;
    asm("cvt.rna.tf32.f32 %0, %1;" : "=r"(u) : "f"(f));
    return __uint_as_float(u);
}

// packed dual-fp32 fma: acc = a * b + acc (elementwise on float2)
__device__ __forceinline__ void fma2(float2& acc, float2 a, float2 b) {
    unsigned long long au = *(unsigned long long*)&a;
    unsigned long long bu = *(unsigned long long*)&b;
    unsigned long long cu = *(unsigned long long*)&acc;
    asm("fma.rn.f32x2 %0, %1, %2, %0;" : "+l"(cu) : "l"(au), "l"(bu));
    acc = *(float2*)&cu;
}

// zero counters + detect int64 vs int32 edge_index
__global__ void init_kernel(const void* eidx) {
    int i = blockIdx.x * blockDim.x + threadIdx.x;
    if (i < NN) { g_cnt[i] = 0; g_cur[i] = 0; }
    if (i == 0) {
        const unsigned* p = (const unsigned*)eidx;
        int is64 = 1;
        for (int k = 0; k < 16; k++)
            if (p[2 * k + 1] != 0u) is64 = 0;
        g_is64 = is64;
    }
}

__global__ void count_kernel(const void* eidx) {
    int e = blockIdx.x * blockDim.x + threadIdx.x;
    if (e >= EE) return;
    int is64 = g_is64;
    int dst = edge_val(eidx, is64, (long long)EE + e);
    atomicAdd(&g_cnt[dst], 1);
}

__global__ __launch_bounds__(1024) void scan_kernel() {
    __shared__ int s[1024];
    int tid = threadIdx.x;
    const int per = (NN + 1023) >> 10;
    int start = tid * per;
    int sum = 0;
    for (int i = 0; i < per; i++) {
        int idx = start + i;
        if (idx < NN) sum += g_cnt[idx];
    }
    s[tid] = sum;
    __syncthreads();
    for (int o = 1; o < 1024; o <<= 1) {
        int v = 0;
        if (tid >= o) v = s[tid - o];
        __syncthreads();
        if (tid >= o) s[tid] += v;
        __syncthreads();
    }
    int base = (tid > 0) ? s[tid - 1] : 0;
    for (int i = 0; i < per; i++) {
        int idx = start + i;
        if (idx < NN) { g_off[idx] = base; base += g_cnt[idx]; }
    }
    if (tid == 1023) g_off[NN] = s[1023];
}

__global__ void scatter_kernel(const void* eidx) {
    int e = blockIdx.x * blockDim.x + threadIdx.x;
    if (e >= EE) return;
    int is64 = g_is64;
    int src = edge_val(eidx, is64, e);
    int dst = edge_val(eidx, is64, (long long)EE + e);
    int pos = g_off[dst] + atomicAdd(&g_cur[dst], 1);
    g_csr_src[pos] = src;
    g_csr_eid[pos] = e;
}

// self-loop attr = mean of incoming edge_attr (CSR-based, no atomics)
__global__ __launch_bounds__(128) void loopattr_kernel(const float* __restrict__ ea) {
    int n = blockIdx.x * 4 + (threadIdx.x >> 5);
    if (n >= NN) return;
    int lane = threadIdx.x & 31;
    int beg = g_off[n], end = g_off[n + 1];
    float sum = 0.f;
    if (lane < EDGE_D) {
        for (int i = beg; i < end; i++) {
            int eid = g_csr_eid[i];
            sum += __ldg(&ea[(size_t)eid * EDGE_D + lane]);
        }
        float c = (float)(end - beg);
        g_loop[n * EDGE_D + lane] = sum / fmaxf(c, 1.f);
    }
}

// fused: tf32-round x into g_xA + pack layer-1 weights/bias
__global__ void prep1_kernel(const float* __restrict__ x,
                             const float* __restrict__ W0, const float* __restrict__ W1,
                             const float* __restrict__ b0, const float* __restrict__ b1) {
    int i = blockIdx.x * blockDim.x + threadIdx.x;
    if (i < NN * NODE_D) g_xA[i] = rna_tf32(x[i]);
    if (i < NODE_D * 1024) {
        int k = i >> 10, j = i & 1023;
        float v = (j < HC) ? W0[k * HC + j] : W1[k * HC + (j - HC)];
        g_Wp[i] = rna_tf32(v);
    }
    if (i < 1024) g_bp[i] = (i < HC) ? b0[i] : b1[i - HC];
}

// pack [W0|W1] (split at col S) into g_Wp with tf32 rounding; bias into g_bp
__global__ void pack_kernel(const float* __restrict__ W0, const float* __restrict__ W1,
                            const float* __restrict__ b0, const float* __restrict__ b1,
                            int S, int Nn, int K) {
    int i = blockIdx.x * blockDim.x + threadIdx.x;
    if (i < K * Nn) {
        int k = i / Nn, j = i - k * Nn;
        float v = (j < S) ? W0[k * S + j] : W1[k * (Nn - S) + (j - S)];
        g_Wp[i] = rna_tf32(v);
    }
    if (i < Nn) g_bp[i] = (i < S) ? b0[i] : b1[i - S];
}

// fused decoder packs: d1 -> g_Wp/g_bp, d2 -> g_Wpd2/g_bpd2
__global__ void packd_kernel(const float* __restrict__ Wd1, const float* __restrict__ bd1,
                             const float* __restrict__ Wd2, const float* __restrict__ bd2) {
    int i = blockIdx.x * blockDim.x + threadIdx.x;
    if (i < HC * HIDDEN) g_Wp[i] = rna_tf32(Wd1[i]);
    if (i < HIDDEN) g_bp[i] = bd1[i];
    if (i < HIDDEN * OUTD) g_Wpd2[i] = rna_tf32(Wd2[i]);
    if (i < OUTD) g_bpd2[i] = bd2[i];
}

// ---------------- tf32 tensor-core GEMM (3-stage cp.async pipeline) -----------
__device__ __forceinline__ void cp16(uint32_t dst, const float* src, int sz) {
    asm volatile("cp.async.cg.shared.global [%0], [%1], 16, %2;\n"
                 :: "r"(dst), "l"(src), "r"(sz));
}
__device__ __forceinline__ void cp_commit() {
    asm volatile("cp.async.commit_group;\n" ::: "memory");
}

template<int BN, int BK, int MINCTA>
__global__ __launch_bounds__(256, MINCTA) void gemm_tc_kernel(
    const float* __restrict__ A, const float* __restrict__ B,
    const float* __restrict__ bias, float* __restrict__ C,
    int M, int Nn, int K, int relu, int round_out)
{
    constexpr int AS_STR = BK + 4;
    constexpr int BS_STR = BN + 8;
    constexpr int A_SZ   = 128 * AS_STR;
    constexpr int STAGE  = A_SZ + BK * BS_STR;
    constexpr int KS     = BK / 8;
    constexpr int NT     = BN / 32;
    constexpr int A_CHUNKS = BK / 8;
    constexpr int TPR_B  = 256 / BK;
    constexpr int B_CHUNKS = BN / TPR_B / 4;

    extern __shared__ float sm[];

    int tid  = threadIdx.x;
    int warp = tid >> 5;
    int lane = tid & 31;
    int gid  = lane >> 2;
    int tg   = lane & 3;

    int warpM = (warp & 1) * 64;
    int warpN = (warp >> 1) * (BN / 4);

    int rowBase = blockIdx.y * 128;
    int colBase = blockIdx.x * BN;

    float acc[4][NT][4];
#pragma unroll
    for (int i = 0; i < 4; i++)
#pragma unroll
        for (int j = 0; j < NT; j++)
#pragma unroll
            for (int r = 0; r < 4; r++) acc[i][j][r] = 0.f;

    int arow = tid >> 1;
    int acol = (tid & 1) * (BK / 2);
    int brow = tid / TPR_B;
    int bcol = (tid % TPR_B) * (BN / TPR_B);
    int agrow = rowBase + arow;
    const float* aptr = A + (size_t)agrow * K + acol;
    int a_sz = (agrow < M) ? 16 : 0;

    uint32_t smem_u = (uint32_t)__cvta_generic_to_shared(sm);
    uint32_t as_u = smem_u + (arow * AS_STR + acol) * 4;
    uint32_t bs_u = smem_u + (A_SZ + brow * BS_STR + bcol) * 4;

    auto load_tiles = [&](int kt, int buf) {
        uint32_t ad = as_u + buf * (STAGE * 4);
        const float* ap = aptr + kt;
#pragma unroll
        for (int i = 0; i < A_CHUNKS; i++) cp16(ad + i * 16, ap + i * 4, a_sz);
        uint32_t bd = bs_u + buf * (STAGE * 4);
        const float* bp = B + (size_t)(kt + brow) * Nn + colBase + bcol;
#pragma unroll
        for (int i = 0; i < B_CHUNKS; i++) {
            int gcol = colBase + bcol + i * 4;
            cp16(bd + i * 16, bp + i * 4, (gcol < Nn) ? 16 : 0);
        }
    };

    int nTiles = K / BK;
    load_tiles(0, 0);
    cp_commit();
    if (nTiles > 1) {
        load_tiles(BK, 1);
        cp_commit();
    }

    int buf = 0;
    for (int t = 0; t < nTiles; t++) {
        if (t + 1 < nTiles) {
            asm volatile("cp.async.wait_group 1;\n" ::: "memory");
        } else {
            asm volatile("cp.async.wait_group 0;\n" ::: "memory");
        }
        __syncthreads();

        if (t + 2 < nTiles) {
            int nbuf = buf + 2; if (nbuf >= 3) nbuf -= 3;
            load_tiles((t + 2) * BK, nbuf);
            cp_commit();
        }

        const float* Ab = sm + buf * STAGE;
        const float* Bb = Ab + A_SZ;
#pragma unroll
        for (int ks = 0; ks < KS; ks++) {
            int k0 = ks * 8;
            unsigned af[4][4], bf[NT][2];
#pragma unroll
            for (int mt = 0; mt < 4; mt++) {
                int r = warpM + mt * 16;
                af[mt][0] = __float_as_uint(Ab[(r + gid) * AS_STR + k0 + tg]);
                af[mt][1] = __float_as_uint(Ab[(r + gid + 8) * AS_STR + k0 + tg]);
                af[mt][2] = __float_as_uint(Ab[(r + gid) * AS_STR + k0 + tg + 4]);
                af[mt][3] = __float_as_uint(Ab[(r + gid + 8) * AS_STR + k0 + tg + 4]);
            }
#pragma unroll
            for (int nt = 0; nt < NT; nt++) {
                int c = warpN + nt * 8;
                bf[nt][0] = __float_as_uint(Bb[(k0 + tg) * BS_STR + c + gid]);
                bf[nt][1] = __float_as_uint(Bb[(k0 + tg + 4) * BS_STR + c + gid]);
            }
#pragma unroll
            for (int mt = 0; mt < 4; mt++)
#pragma unroll
                for (int nt = 0; nt < NT; nt++) {
                    asm volatile(
                        "mma.sync.aligned.m16n8k8.row.col.f32.tf32.tf32.f32 "
                        "{%0,%1,%2,%3}, {%4,%5,%6,%7}, {%8,%9}, {%0,%1,%2,%3};"
                        : "+f"(acc[mt][nt][0]), "+f"(acc[mt][nt][1]),
                          "+f"(acc[mt][nt][2]), "+f"(acc[mt][nt][3])
                        : "r"(af[mt][0]), "r"(af[mt][1]), "r"(af[mt][2]), "r"(af[mt][3]),
                          "r"(bf[nt][0]), "r"(bf[nt][1]));
                }
        }
        buf++; if (buf >= 3) buf -= 3;
    }

    // epilogue
#pragma unroll
    for (int mt = 0; mt < 4; mt++) {
#pragma unroll
        for (int nt = 0; nt < NT; nt++) {
            int r0 = rowBase + warpM + mt * 16 + gid;
            int c0 = colBase + warpN + nt * 8 + tg * 2;
#pragma unroll
            for (int half = 0; half < 2; half++) {
                int row = r0 + half * 8;
                if (row < M) {
#pragma unroll
                    for (int j = 0; j < 2; j++) {
                        int col = c0 + j;
                        if (col < Nn) {
                            float v = acc[mt][nt][half * 2 + j] + bias[col];
                            if (relu) v = fmaxf(v, 0.f);
                            if (round_out) v = rna_tf32(v);
                            C[(size_t)row * Nn + col] = v;
                        }
                    }
                }
            }
        }
    }
}

#define SMEM_OF(BN, BK) (3 * (128 * ((BK) + 4) + (BK) * ((BN) + 8)) * 4)

// ---------------- GATv2 aggregation: 2 nodes / block, 4 edges / iteration ----
// ef inner loop uses packed fma.rn.f32x2 (dual-fp32 FMA) to halve fma-pipe load.
__global__ __launch_bounds__(256) void gat_kernel(
    const float* __restrict__ xlr,        // [N][1024] xl|xr
    const float* __restrict__ edge_attr,  // [E][16]
    const float* __restrict__ We,         // [16][512]
    const float* __restrict__ att,        // [512]
    const float* __restrict__ bias,       // [512]
    float* __restrict__ out)              // [N][512] (tf32-rounded: feeds GEMMs only)
{
    __shared__ float We_sh[EDGE_D * HC];
    for (int i = threadIdx.x; i < EDGE_D * HC; i += 256) We_sh[i] = We[i];
    __syncthreads();

    int w = (threadIdx.x >> 5) & 3;           // head
    int lane = threadIdx.x & 31;
    int n = blockIdx.x * 2 + (threadIdx.x >> 7);   // node
    if (n >= NN) return;
    int cbase = w * EMB + lane;
    const float* Wp = We_sh + cbase;

    float att0 = __ldg(&att[cbase]);
    float att1 = __ldg(&att[cbase + 32]);
    float att2 = __ldg(&att[cbase + 64]);
    float att3 = __ldg(&att[cbase + 96]);

    const float* xrp = xlr + (size_t)n * 1024 + HC + cbase;
    float xr0 = xrp[0], xr1 = xrp[32], xr2 = xrp[64], xr3 = xrp[96];

    float m = -CUDART_INF_F, den = 0.f;
    float a0 = 0.f, a1 = 0.f, a2 = 0.f, a3 = 0.f;

    int beg = g_off[n], end = g_off[n + 1];

    for (int i = beg; i <= end; i += 4) {
        // load up to 4 edges (invalid slots -> zeros; masked out at softmax)
        float ce[4];
        float cx[4][4];
#pragma unroll
        for (int j = 0; j < 4; j++) {
            int idx = i + j;
            if (idx <= end) {
                int src;
                const float* ea;
                if (idx < end) {
                    src = __ldg(&g_csr_src[idx]);
                    ea  = edge_attr + (size_t)__ldg(&g_csr_eid[idx]) * EDGE_D;
                } else {
                    src = n;
                    ea  = g_loop + (size_t)n * EDGE_D;
                }
                ce[j] = (lane < EDGE_D) ? __ldg(&ea[lane]) : 0.f;
                const float* xp = xlr + (size_t)src * 1024 + cbase;
                cx[j][0] = __ldg(&xp[0]);  cx[j][1] = __ldg(&xp[32]);
                cx[j][2] = __ldg(&xp[64]); cx[j][3] = __ldg(&xp[96]);
            } else {
                ce[j] = 0.f;
                cx[j][0] = cx[j][1] = cx[j][2] = cx[j][3] = 0.f;
            }
        }

        // ef accumulators as channel-pairs (init with xr)
        float2 e01[4], e23[4];
#pragma unroll
        for (int j = 0; j < 4; j++) {
            e01[j] = make_float2(xr0, xr1);
            e23[j] = make_float2(xr2, xr3);
        }
#pragma unroll
        for (int d = 0; d < EDGE_D; d++) {
            float2 w01 = make_float2(Wp[d * HC],      Wp[d * HC + 32]);
            float2 w23 = make_float2(Wp[d * HC + 64], Wp[d * HC + 96]);
#pragma unroll
            for (int j = 0; j < 4; j++) {
                float av = __shfl_sync(0xffffffffu, ce[j], d);
                float2 av2 = make_float2(av, av);
                fma2(e01[j], av2, w01);
                fma2(e23[j], av2, w23);
            }
        }

        float p[4];
#pragma unroll
        for (int j = 0; j < 4; j++) {
            float s0 = cx[j][0] + e01[j].x;
            float s1 = cx[j][1] + e01[j].y;
            float s2 = cx[j][2] + e23[j].x;
            float s3 = cx[j][3] + e23[j].y;
            float l0 = fmaxf(s0, NEG_SLOPE * s0);
            float l1 = fmaxf(s1, NEG_SLOPE * s1);
            float l2 = fmaxf(s2, NEG_SLOPE * s2);
            float l3 = fmaxf(s3, NEG_SLOPE * s3);
            float pv = l0 * att0;
            pv = fmaf(l1, att1, pv);
            pv = fmaf(l2, att2, pv);
            pv = fmaf(l3, att3, pv);
            p[j] = pv;
        }
#pragma unroll
        for (int o = 16; o > 0; o >>= 1) {
#pragma unroll
            for (int j = 0; j < 4; j++)
                p[j] += __shfl_xor_sync(0xffffffffu, p[j], o);
        }
#pragma unroll
        for (int j = 0; j < 4; j++)
            if (i + j > end) p[j] = -CUDART_INF_F;

        float nm = fmaxf(fmaxf(m, fmaxf(p[0], p[1])), fmaxf(p[2], p[3]));
        float corr = __expf(m - nm);
        float pe0 = __expf(p[0] - nm);
        float pe1 = __expf(p[1] - nm);
        float pe2 = __expf(p[2] - nm);
        float pe3 = __expf(p[3] - nm);
        den = den * corr + pe0 + pe1 + pe2 + pe3;
        a0 = a0 * corr + pe0 * cx[0][0] + pe1 * cx[1][0] + pe2 * cx[2][0] + pe3 * cx[3][0];
        a1 = a1 * corr + pe0 * cx[0][1] + pe1 * cx[1][1] + pe2 * cx[2][1] + pe3 * cx[3][1];
        a2 = a2 * corr + pe0 * cx[0][2] + pe1 * cx[1][2] + pe2 * cx[2][2] + pe3 * cx[3][2];
        a3 = a3 * corr + pe0 * cx[0][3] + pe1 * cx[1][3] + pe2 * cx[2][3] + pe3 * cx[3][3];
        m = nm;
    }
    float inv = 1.f / (den + 1e-16f);
    float* op = out + (size_t)n * HC + cbase;
    op[0]  = rna_tf32(fmaf(a0, inv, __ldg(&bias[cbase])));
    op[32] = rna_tf32(fmaf(a1, inv, __ldg(&bias[cbase + 32])));
    op[64] = rna_tf32(fmaf(a2, inv, __ldg(&bias[cbase + 64])));
    op[96] = rna_tf32(fmaf(a3, inv, __ldg(&bias[cbase + 96])));
}

// ---------------- launch ------------------------------------------------------
extern "C" void kernel_launch(void* const* d_in, const int* in_sizes, int n_in,
                              void* d_out, int out_size) {
    const float* x     = (const float*)d_in[0];
    const void*  eidx  = d_in[1];
    const float* eattr = (const float*)d_in[2];
    const float* Wl1   = (const float*)d_in[3];
    const float* bl1   = (const float*)d_in[4];
    const float* Wr1   = (const float*)d_in[5];
    const float* br1   = (const float*)d_in[6];
    const float* We1   = (const float*)d_in[7];
    const float* att1  = (const float*)d_in[8];
    const float* bias1 = (const float*)d_in[9];
    const float* Wl2   = (const float*)d_in[10];
    const float* bl2   = (const float*)d_in[11];
    const float* Wr2   = (const float*)d_in[12];
    const float* br2   = (const float*)d_in[13];
    const float* We2   = (const float*)d_in[14];
    const float* att2  = (const float*)d_in[15];
    const float* bias2 = (const float*)d_in[16];
    const float* Wd1   = (const float*)d_in[17];
    const float* bd1   = (const float*)d_in[18];
    const float* Wd2   = (const float*)d_in[19];
    const float* bd2   = (const float*)d_in[20];
    float* out = (float*)d_out;

    float* xlr; cudaGetSymbolAddress((void**)&xlr, g_xlr);
    float* h;   cudaGetSymbolAddress((void**)&h, g_h);
    float* xA;  cudaGetSymbolAddress((void**)&xA, g_xA);
    float* Wp;  cudaGetSymbolAddress((void**)&Wp, g_Wp);
    float* bp;  cudaGetSymbolAddress((void**)&bp, g_bp);
    float* Wpd2; cudaGetSymbolAddress((void**)&Wpd2, g_Wpd2);
    float* bpd2; cudaGetSymbolAddress((void**)&bpd2, g_bpd2);

    cudaFuncSetAttribute((const void*)gemm_tc_kernel<128, 32, 2>,
                         cudaFuncAttributeMaxDynamicSharedMemorySize, SMEM_OF(128, 32));
    cudaFuncSetAttribute((const void*)gemm_tc_kernel<64, 32, 2>,
                         cudaFuncAttributeMaxDynamicSharedMemorySize, SMEM_OF(64, 32));

    dim3 blk(256);
    dim3 grid_lr(1024 / 128, (NN + 127) / 128);
    dim3 grid_d1(HIDDEN / 128, (NN + 127) / 128);
    dim3 grid_d2(1, (NN + 127) / 128);   // OUTD=64 = BN

    // ---- layer-1 GEMM early (ncu capture lands nearby) ----
    init_kernel<<<(NN + 255) / 256, 256>>>(eidx);
    prep1_kernel<<<(NN * NODE_D + 255) / 256, 256>>>(x, Wl1, Wr1, bl1, br1);
    count_kernel<<<(EE + 255) / 256, 256>>>(eidx);
    gemm_tc_kernel<128, 32, 2><<<grid_lr, blk, SMEM_OF(128, 32)>>>(xA, Wp, bp, xlr, NN, 1024, NODE_D, 0, 0);

    // ---- CSR preprocessing ----
    scan_kernel<<<1, 1024>>>();
    scatter_kernel<<<(EE + 255) / 256, 256>>>(eidx);
    loopattr_kernel<<<(NN + 3) / 4, 128>>>(eattr);

    // ---- layer 1 aggregation ----
    gat_kernel<<<NN / 2, 256>>>(xlr, eattr, We1, att1, bias1, h);

    // ---- layer 2 ----
    pack_kernel<<<(HC * 1024 + 255) / 256, 256>>>(Wl2, Wr2, bl2, br2, HC, 1024, HC);
    gemm_tc_kernel<128, 32, 2><<<grid_lr, blk, SMEM_OF(128, 32)>>>(h, Wp, bp, xlr, NN, 1024, HC, 0, 0);
    gat_kernel<<<NN / 2, 256>>>(xlr, eattr, We2, att2, bias2, h);

    // ---- decoder ----
    float* hid = xlr;  // reuse scratch
    packd_kernel<<<(HC * HIDDEN + 255) / 256, 256>>>(Wd1, bd1, Wd2, bd2);
    gemm_tc_kernel<128, 32, 2><<<grid_d1, blk, SMEM_OF(128, 32)>>>(h, Wp, bp, hid, NN, HIDDEN, HC, 1, 1);
    gemm_tc_kernel<64, 32, 2><<<grid_d2, blk, SMEM_OF(64, 32)>>>(hid, Wpd2, bpd2, out, NN, OUTD, HIDDEN, 0, 0);
}